// round 9
// baseline (speedup 1.0000x reference)
#include <cuda_runtime.h>
#include <stdint.h>

// Problem constants
#define BB 32
#define NN 1024
#define DD 768
#define D4 (DD/4)          // 192 float4 per row
#define KMASK 768          // masked tokens per row
#define NUNM  256          // unmasked tokens per row

// Output layout (float32 concat of the 5 reference outputs, flattened in order)
#define OFF_WITHMASK 0ull
#define OFF_UNMP   ((unsigned long long)BB*NN*DD)                       // 25165824
#define OFF_BOOL   (OFF_UNMP + (unsigned long long)BB*NUNM*DD)          // 31457280
#define OFF_MIDX   (OFF_BOOL + (unsigned long long)BB*NN*DD)            // 56623104
#define OFF_UIDX   (OFF_MIDX + (unsigned long long)BB*KMASK)            // 56647680

// Scratch (zero-initialized; flags/counters restored each run)
__device__ int g_info[BB * NN];   // -1 => masked; else rank among unmasked
__device__ int g_flag[BB];        // batch b sort complete
__device__ int g_done[BB];        // per-batch consumer completion count

// ---------------------------------------------------------------------------
// Kernel 1 (producer): hybrid register/shuffle bitonic argsort + finalize.
// One 1024-thread block per batch row. Triggers PDL completion at the START
// so the scatter grid launches concurrently; per-batch results are released
// via g_flag with a threadfence.
// ---------------------------------------------------------------------------
__global__ __launch_bounds__(1024, 1)
void mask_sort_kernel(const float* __restrict__ noise, float* __restrict__ out)
{
    // Let the dependent scatter grid start launching right away.
    cudaTriggerProgrammaticLaunchCompletion();

    __shared__ unsigned long long sbuf[2][NN];
    __shared__ int warp_sums[32];

    const int b = blockIdx.x;
    const int t = threadIdx.x;

    float v = noise[b * NN + t];
    unsigned long long key =
        ((unsigned long long)__float_as_uint(v) << 32) | (unsigned)t;

    int p = 0;
    #pragma unroll 1
    for (int k = 2; k <= NN; k <<= 1) {
        const bool up = ((t & k) == 0);
        #pragma unroll 1
        for (int j = k >> 1; j > 0; j >>= 1) {
            unsigned long long other;
            if (j >= 32) {
                sbuf[p][t] = key;
                __syncthreads();
                other = sbuf[p][t ^ j];
                p ^= 1;
            } else {
                other = __shfl_xor_sync(0xFFFFFFFFu, key, j);
            }
            const bool lower = ((t & j) == 0);
            const bool keep_small = (up == lower);
            const bool take = keep_small ? (other < key) : (other > key);
            if (take) key = other;
        }
    }

    // key = t-th smallest; perm[t] = its original index
    int perm = (int)(key & 0xFFFFFFFFu);
    int m = (perm < KMASK) ? 1 : 0;   // bool_mask at position t

    // Exclusive prefix sum of m (ballot + warp sums)
    const int lane = t & 31;
    const int warp = t >> 5;
    unsigned ballot = __ballot_sync(0xFFFFFFFFu, m);
    int before_in_warp = __popc(ballot & ((1u << lane) - 1u));
    if (lane == 0) warp_sums[warp] = __popc(ballot);
    __syncthreads();
    int warp_before = 0;
    #pragma unroll
    for (int w = 0; w < 32; ++w)
        warp_before += (w < warp) ? warp_sums[w] : 0;
    int t_before = warp_before + before_in_warp;

    // order = stable argsort(bool_mask): False positions first, then True.
    float* masked_out = out + OFF_MIDX;
    float* unm_out    = out + OFF_UIDX;
    if (m) {
        masked_out[b * KMASK + t_before] = (float)t;
        g_info[b * NN + t] = -1;
    } else {
        int r = t - t_before;
        unm_out[b * NUNM + r] = (float)t;
        g_info[b * NN + t] = r;
    }

    // Release this batch's g_info to the scatter blocks.
    __syncthreads();
    if (t == 0) {
        __threadfence();
        atomicExch(&g_flag[b], 1);
    }
}

// ---------------------------------------------------------------------------
// Kernel 2 (consumer): scatter, one token per block (32768 x 192 thr).
// Runs concurrently with the sort; thread 0 spins on the batch flag, then the
// block streams fully-coalesced float4 rows. g_info is read with __ldcg
// (L2-coherent) — NOT __ldg, since it is produced by a concurrent kernel.
// Last consumer block of each batch resets flag/done for graph replay.
// ---------------------------------------------------------------------------
__global__ __launch_bounds__(192, 10)
void mask_scatter_kernel(const float* __restrict__ patch,
                         const float* __restrict__ mask_emb,
                         float* __restrict__ out)
{
    const int tok = blockIdx.x;          // b*N + j
    const int b   = tok >> 10;
    const int t   = threadIdx.x;         // float4 lane 0..191

    // Truly immutable input — safe on the fast path; issue while waiting.
    const float4 me = __ldg(reinterpret_cast<const float4*>(mask_emb) + t);

    if (t == 0) {
        while (atomicOr(&g_flag[b], 0) == 0) { __nanosleep(64); }
        __threadfence();                  // acquire
    }
    __syncthreads();

    // Coherent (L2) load of concurrently-produced data.
    const int info = __ldcg(&g_info[tok]);

    float4* wm = reinterpret_cast<float4*>(out + OFF_WITHMASK) + (size_t)tok * D4;
    float4* be = reinterpret_cast<float4*>(out + OFF_BOOL)     + (size_t)tok * D4;

    const float bv = (info < 0) ? 1.0f : 0.0f;
    __stcs(be + t, make_float4(bv, bv, bv, bv));

    if (info < 0) {
        __stcs(wm + t, me);
    } else {
        float4 pch = __ldcs(reinterpret_cast<const float4*>(patch) + (size_t)tok * D4 + t);
        __stcs(wm + t, pch);
        float4* up = reinterpret_cast<float4*>(out + OFF_UNMP)
                   + ((size_t)b * NUNM + info) * D4;
        __stcs(up + t, pch);
    }

    // Restore handshake state for the next graph replay.
    __syncthreads();
    if (t == 0) {
        int d = atomicAdd(&g_done[b], 1);
        if (d == NN - 1) {                // last consumer block of batch b
            atomicExch(&g_done[b], 0);
            atomicExch(&g_flag[b], 0);
        }
    }
}

extern "C" void kernel_launch(void* const* d_in, const int* in_sizes, int n_in,
                              void* d_out, int out_size)
{
    const float* patch    = (const float*)d_in[0];  // (B, N, D) f32
    const float* noise    = (const float*)d_in[1];  // (B, N)    f32
    const float* mask_emb = (const float*)d_in[2];  // (D,)      f32
    float* out = (float*)d_out;

    // Primary: triggers PDL completion at its start.
    mask_sort_kernel<<<BB, 1024>>>(noise, out);

    // Secondary: launches as soon as the primary triggers; data dependency is
    // enforced per-batch by the g_flag handshake, not by the launch boundary.
    cudaLaunchAttribute attrs[1];
    attrs[0].id = cudaLaunchAttributeProgrammaticStreamSerialization;
    attrs[0].val.programmaticStreamSerializationAllowed = 1;

    cudaLaunchConfig_t cfg = {};
    cfg.gridDim  = dim3(BB * NN, 1, 1);
    cfg.blockDim = dim3(192, 1, 1);
    cfg.dynamicSmemBytes = 0;
    cfg.stream = 0;
    cfg.attrs = attrs;
    cfg.numAttrs = 1;

    cudaLaunchKernelEx(&cfg, mask_scatter_kernel, patch, mask_emb, out);
}

// round 12
// speedup vs baseline: 1.0342x; 1.0342x over previous
#include <cuda_runtime.h>
#include <stdint.h>

// Problem constants
#define BB 32
#define NN 1024
#define DD 768
#define D4 (DD/4)          // 192 float4 per row
#define KMASK 768          // masked tokens per row
#define NUNM  256          // unmasked tokens per row

#define NBLK 296           // 2 CTAs/SM x 148 SMs: all wave-1 resident
#define TPB  111           // tokens per block (295*111=32745, last block 23)

// Output layout (float32 concat of the 5 reference outputs, flattened in order)
#define OFF_WITHMASK 0ull
#define OFF_UNMP   ((unsigned long long)BB*NN*DD)                       // 25165824
#define OFF_BOOL   (OFF_UNMP + (unsigned long long)BB*NUNM*DD)          // 31457280
#define OFF_MIDX   (OFF_BOOL + (unsigned long long)BB*NN*DD)            // 56623104
#define OFF_UIDX   (OFF_MIDX + (unsigned long long)BB*KMASK)            // 56647680

// Scratch (zero-initialized; restored at end of every run for graph replay)
__device__ int g_info[BB * NN];   // -1 => masked; else rank among unmasked
__device__ int g_flag[BB];        // batch b sort complete
__device__ int g_done;            // finished-block count

__global__ __launch_bounds__(1024, 2)
void mask_fused_kernel(const float* __restrict__ patch,
                       const float* __restrict__ noise,
                       const float* __restrict__ mask_emb,
                       float* __restrict__ out)
{
    __shared__ unsigned long long sbuf[2][NN];   // sort exchange (16 KB)
    __shared__ int warp_sums[32];
    __shared__ float4 s_me[D4];                  // mask_emb (3 KB)
    __shared__ int s_info[TPB + 1];

    const int t   = threadIdx.x;
    const int bid = blockIdx.x;

    // ---------------- Phase 1 (blocks 0..31): sort batch b ----------------
    if (bid < BB) {
        const int b = bid;

        float v = noise[b * NN + t];
        unsigned long long key =
            ((unsigned long long)__float_as_uint(v) << 32) | (unsigned)t;

        int p = 0;
        #pragma unroll 1
        for (int k = 2; k <= NN; k <<= 1) {
            const bool up = ((t & k) == 0);
            #pragma unroll 1
            for (int j = k >> 1; j > 0; j >>= 1) {
                unsigned long long other;
                if (j >= 32) {
                    sbuf[p][t] = key;
                    __syncthreads();
                    other = sbuf[p][t ^ j];
                    p ^= 1;
                } else {
                    other = __shfl_xor_sync(0xFFFFFFFFu, key, j);
                }
                const bool lower = ((t & j) == 0);
                const bool keep_small = (up == lower);
                const bool take = keep_small ? (other < key) : (other > key);
                if (take) key = other;
            }
        }

        int perm = (int)(key & 0xFFFFFFFFu);
        int m = (perm < KMASK) ? 1 : 0;          // bool_mask at position t

        const int lane = t & 31;
        const int warp = t >> 5;
        unsigned ballot = __ballot_sync(0xFFFFFFFFu, m);
        int before_in_warp = __popc(ballot & ((1u << lane) - 1u));
        if (lane == 0) warp_sums[warp] = __popc(ballot);
        __syncthreads();
        int warp_before = 0;
        #pragma unroll
        for (int w = 0; w < 32; ++w)
            warp_before += (w < warp) ? warp_sums[w] : 0;
        int t_before = warp_before + before_in_warp;

        float* masked_out = out + OFF_MIDX;
        float* unm_out    = out + OFF_UIDX;
        if (m) {
            masked_out[b * KMASK + t_before] = (float)t;
            g_info[b * NN + t] = -1;
        } else {
            int r = t - t_before;
            unm_out[b * NUNM + r] = (float)t;
            g_info[b * NN + t] = r;
        }

        __syncthreads();
        if (t == 0) {
            __threadfence();
            atomicExch(&g_flag[b], 1);
        }
    }

    // ---------------- Phase 2 (all blocks): scatter token slice ----------------
    const int tok0 = bid * TPB;
    const int ntok = min(TPB, BB * NN - tok0);   // 23 for the last block

    // Preload mask_emb (immutable input) before waiting.
    if (t < D4)
        s_me[t] = __ldg(reinterpret_cast<const float4*>(mask_emb) + t);

    // Wait for the (at most 2) batches this slice touches. Only NBLK pollers.
    const int b0 = tok0 >> 10;
    const int b1 = (tok0 + ntok - 1) >> 10;
    if (t == 0) {
        while (atomicOr(&g_flag[b0], 0) == 0) { __nanosleep(128); }
        if (b1 != b0)
            while (atomicOr(&g_flag[b1], 0) == 0) { __nanosleep(128); }
        __threadfence();                          // acquire
    }
    __syncthreads();

    // Coherent preload of this slice's token info into smem.
    if (t < ntok) s_info[t] = __ldcg(&g_info[tok0 + t]);
    __syncthreads();

    float4* wm_base = reinterpret_cast<float4*>(out + OFF_WITHMASK);
    float4* be_base = reinterpret_cast<float4*>(out + OFF_BOOL);
    float4* up_base = reinterpret_cast<float4*>(out + OFF_UNMP);
    const float4* patch4 = reinterpret_cast<const float4*>(patch);

    const size_t base = (size_t)tok0 * D4;
    const int nelem = ntok * D4;                 // float4 elements in slice

    #pragma unroll 1
    for (int e = t; e < nelem; e += 1024) {
        const int tl   = e / D4;                 // token within slice
        const int lane = e - tl * D4;            // float4 lane 0..191
        const int info = s_info[tl];
        const size_t g = base + e;

        const float bv = (info < 0) ? 1.0f : 0.0f;
        __stcs(be_base + g, make_float4(bv, bv, bv, bv));

        if (info < 0) {
            __stcs(wm_base + g, s_me[lane]);
        } else {
            float4 pch = __ldcs(patch4 + g);
            __stcs(wm_base + g, pch);
            const int b = (tok0 + tl) >> 10;
            __stcs(up_base + ((size_t)b * NUNM + info) * D4 + lane, pch);
        }
    }

    // ---------------- Reset handshake state for graph replay ----------------
    __syncthreads();
    if (t == 0) {
        int d = atomicAdd(&g_done, 1);
        if (d == NBLK - 1) {                     // last block to finish
            #pragma unroll
            for (int b = 0; b < BB; ++b) atomicExch(&g_flag[b], 0);
            atomicExch(&g_done, 0);
        }
    }
}

extern "C" void kernel_launch(void* const* d_in, const int* in_sizes, int n_in,
                              void* d_out, int out_size)
{
    const float* patch    = (const float*)d_in[0];  // (B, N, D) f32
    const float* noise    = (const float*)d_in[1];  // (B, N)    f32
    const float* mask_emb = (const float*)d_in[2];  // (D,)      f32
    float* out = (float*)d_out;

    mask_fused_kernel<<<NBLK, 1024>>>(patch, noise, mask_emb, out);
}

// round 13
// speedup vs baseline: 1.1706x; 1.1319x over previous
#include <cuda_runtime.h>
#include <stdint.h>

// Problem constants
#define BB 32
#define NN 1024
#define DD 768
#define D4 (DD/4)          // 192 float4 per row
#define KMASK 768          // masked tokens per row
#define NUNM  256          // unmasked tokens per row

#define TOKB 4             // tokens per scatter block
#define SCAT_THREADS 256
#define SCAT_ITERS 3       // 4 tokens * 192 f4 = 768 = 3 * 256

// Output layout (float32 concat of the 5 reference outputs, flattened in order)
#define OFF_WITHMASK 0ull
#define OFF_UNMP   ((unsigned long long)BB*NN*DD)                       // 25165824
#define OFF_BOOL   (OFF_UNMP + (unsigned long long)BB*NUNM*DD)          // 31457280
#define OFF_MIDX   (OFF_BOOL + (unsigned long long)BB*NN*DD)            // 56623104
#define OFF_UIDX   (OFF_MIDX + (unsigned long long)BB*KMASK)            // 56647680

// Scratch: per-token info. -1 => masked; else rank among unmasked (0..255)
__device__ int g_info[BB * NN];

// ---------------------------------------------------------------------------
// Kernel 1: hybrid register/shuffle bitonic argsort + fused finalize.
// One 1024-thread block per batch row (verified correct R3..R12).
// PDL completion triggered at the END (R6 semantics: scatter's launch/prologue
// overlaps the sort, but its g_info reads happen strictly after).
// ---------------------------------------------------------------------------
__global__ __launch_bounds__(1024, 1)
void mask_sort_kernel(const float* __restrict__ noise, float* __restrict__ out)
{
    __shared__ unsigned long long sbuf[2][NN];
    __shared__ int warp_sums[32];

    const int b = blockIdx.x;
    const int t = threadIdx.x;

    float v = noise[b * NN + t];
    unsigned long long key =
        ((unsigned long long)__float_as_uint(v) << 32) | (unsigned)t;

    int p = 0;
    #pragma unroll 1
    for (int k = 2; k <= NN; k <<= 1) {
        const bool up = ((t & k) == 0);
        #pragma unroll 1
        for (int j = k >> 1; j > 0; j >>= 1) {
            unsigned long long other;
            if (j >= 32) {
                sbuf[p][t] = key;
                __syncthreads();
                other = sbuf[p][t ^ j];
                p ^= 1;
            } else {
                other = __shfl_xor_sync(0xFFFFFFFFu, key, j);
            }
            const bool lower = ((t & j) == 0);
            const bool keep_small = (up == lower);
            const bool take = keep_small ? (other < key) : (other > key);
            if (take) key = other;
        }
    }

    // key = t-th smallest; perm[t] = its original index
    int perm = (int)(key & 0xFFFFFFFFu);
    int m = (perm < KMASK) ? 1 : 0;   // bool_mask at position t

    // Exclusive prefix sum of m (ballot + warp sums)
    const int lane = t & 31;
    const int warp = t >> 5;
    unsigned ballot = __ballot_sync(0xFFFFFFFFu, m);
    int before_in_warp = __popc(ballot & ((1u << lane) - 1u));
    if (lane == 0) warp_sums[warp] = __popc(ballot);
    __syncthreads();
    int warp_before = 0;
    #pragma unroll
    for (int w = 0; w < 32; ++w)
        warp_before += (w < warp) ? warp_sums[w] : 0;
    int t_before = warp_before + before_in_warp;

    // order = stable argsort(bool_mask): False positions first, then True.
    float* masked_out = out + OFF_MIDX;
    float* unm_out    = out + OFF_UIDX;
    if (m) {
        masked_out[b * KMASK + t_before] = (float)t;
        g_info[b * NN + t] = -1;
    } else {
        int r = t - t_before;
        unm_out[b * NUNM + r] = (float)t;
        g_info[b * NN + t] = r;
    }

    cudaTriggerProgrammaticLaunchCompletion();
}

// ---------------------------------------------------------------------------
// Kernel 2: scatter, 4 tokens per 256-thread block (8192 blocks, 8 CTAs/SM =
// 2048 threads). Dependency chain batched for MLP: 4 info loads -> barrier ->
// all 3 iterations' patch loads issued up front (predicated) -> all stores.
// Plain (caching) loads/stores: sort kernel fully precedes (PDL trigger at
// end), and leaving dirty lines in the 126MB L2 lets the drain overlap.
// ---------------------------------------------------------------------------
__global__ __launch_bounds__(SCAT_THREADS, 8)
void mask_scatter_kernel(const float* __restrict__ patch,
                         const float* __restrict__ mask_emb,
                         float* __restrict__ out)
{
    __shared__ float4 s_me[D4];
    __shared__ int s_info[TOKB];

    const int tok0 = blockIdx.x * TOKB;          // 4 | 1024 -> single batch
    const int b    = tok0 >> 10;
    const int t    = threadIdx.x;

    // mask_emb is sort-independent: load before the grid dependency resolves.
    if (t < D4)
        s_me[t] = __ldg(reinterpret_cast<const float4*>(mask_emb) + t);

    cudaGridDependencySynchronize();

    if (t < TOKB) s_info[t] = __ldg(&g_info[tok0 + t]);
    __syncthreads();

    const float4* patch4 = reinterpret_cast<const float4*>(patch);
    float4* wm_base = reinterpret_cast<float4*>(out + OFF_WITHMASK);
    float4* be_base = reinterpret_cast<float4*>(out + OFF_BOOL);
    float4* up_base = reinterpret_cast<float4*>(out + OFF_UNMP);

    const size_t base = (size_t)tok0 * D4;       // block-contiguous region

    // Phase A: gather per-iteration metadata and issue ALL patch loads (MLP=3).
    int   infos[SCAT_ITERS];
    int   lanes[SCAT_ITERS];
    size_t gidx[SCAT_ITERS];
    float4 pch[SCAT_ITERS];

    #pragma unroll
    for (int it = 0; it < SCAT_ITERS; ++it) {
        const int e  = it * SCAT_THREADS + t;    // 0..767
        const int tl = e / D4;                   // token 0..3
        lanes[it] = e - tl * D4;
        infos[it] = s_info[tl];
        gidx[it]  = base + e;
        if (infos[it] >= 0)
            pch[it] = patch4[gidx[it]];
    }

    // Phase B: all stores (bool rows, with_mask rows, unmasked scatter).
    #pragma unroll
    for (int it = 0; it < SCAT_ITERS; ++it) {
        const int info = infos[it];
        const float bv = (info < 0) ? 1.0f : 0.0f;
        be_base[gidx[it]] = make_float4(bv, bv, bv, bv);

        if (info < 0) {
            wm_base[gidx[it]] = s_me[lanes[it]];
        } else {
            wm_base[gidx[it]] = pch[it];
            up_base[((size_t)b * NUNM + info) * D4 + lanes[it]] = pch[it];
        }
    }
}

extern "C" void kernel_launch(void* const* d_in, const int* in_sizes, int n_in,
                              void* d_out, int out_size)
{
    const float* patch    = (const float*)d_in[0];  // (B, N, D) f32
    const float* noise    = (const float*)d_in[1];  // (B, N)    f32
    const float* mask_emb = (const float*)d_in[2];  // (D,)      f32
    float* out = (float*)d_out;

    // Primary: sort (PDL completion at its end).
    mask_sort_kernel<<<BB, 1024>>>(noise, out);

    // Secondary: PDL — launch/prologue overlaps the sort; g_info reads are
    // ordered by cudaGridDependencySynchronize.
    cudaLaunchAttribute attrs[1];
    attrs[0].id = cudaLaunchAttributeProgrammaticStreamSerialization;
    attrs[0].val.programmaticStreamSerializationAllowed = 1;

    cudaLaunchConfig_t cfg = {};
    cfg.gridDim  = dim3(BB * NN / TOKB, 1, 1);
    cfg.blockDim = dim3(SCAT_THREADS, 1, 1);
    cfg.dynamicSmemBytes = 0;
    cfg.stream = 0;
    cfg.attrs = attrs;
    cfg.numAttrs = 1;

    cudaLaunchKernelEx(&cfg, mask_scatter_kernel, patch, mask_emb, out);
}